// round 13
// baseline (speedup 1.0000x reference)
#include <cuda_runtime.h>
#include <cuda_bf16.h>

// SoftDecisionML10: argmax_k <x, c_k> over 32 fixed +-1 codewords, output row.
// Codebook: c[k][0..4]=sign(b4..b0), c[k][5..9]=sign(b0^b4,b3^b4,b2^b3,b1^b2,b0^b1)
// Correlations via 32-pt WHT of 10-sparse vector; t = WHT = -score -> argmin t.
// Bits via per-bit half-min vs global min (strict > keeps smallest index, matching
// jnp.argmax tie-break). XOR cols: sign(bi^bj) = -(si*sj).
//
// Memory: warp-autonomous 128-point tiles (5120B/warp smem, reused in->out).
// 10 LDG.128 issued back-to-back per warp (MLP=10) to cover DRAM latency --
// R11 showed the kernel is latency-bound (nothing saturated), so the fix is
// more outstanding loads per warp, not fewer barriers. Each lane computes two
// 2-point groups at f4 offsets lane*5 and 160+lane*5: both are the
// conflict-free 20*lane mod 32 bank pattern for LDS.128/STS.128.

#define TPB 256
#define WARPS_PER_BLK (TPB / 32)
#define PPT 4
#define PTS_PER_WARP (32 * PPT)                     // 128 points
#define F4_PER_WARP (PTS_PER_WARP * 10 / 4)         // 320 float4 = 5120B
#define PTS_PER_BLK (WARPS_PER_BLK * PTS_PER_WARP)  // 1024

__device__ __forceinline__ void decide10(const float* __restrict__ x,
                                         float* __restrict__ o)
{
    float v[32];
    #pragma unroll
    for (int i = 0; i < 32; i++) v[i] = 0.0f;
    v[16] = x[0];
    v[8]  = x[1];
    v[4]  = x[2];
    v[2]  = x[3];
    v[1]  = x[4];
    v[17] = x[5];
    v[24] = x[6];
    v[12] = x[7];
    v[6]  = x[8];
    v[3]  = x[9];

    #pragma unroll
    for (int s = 1; s < 32; s <<= 1) {
        #pragma unroll
        for (int i = 0; i < 32; i++) {
            if ((i & s) == 0) {
                float a = v[i], b = v[i | s];
                v[i]     = a + b;
                v[i | s] = a - b;
            }
        }
    }

    float L1[16];
    #pragma unroll
    for (int i = 0; i < 16; i++) L1[i] = fminf(v[2*i], v[2*i+1]);
    float L2[8];
    #pragma unroll
    for (int i = 0; i < 8; i++)  L2[i] = fminf(L1[2*i], L1[2*i+1]);
    float L3[4];
    #pragma unroll
    for (int i = 0; i < 4; i++)  L3[i] = fminf(L2[2*i], L2[2*i+1]);
    float L40 = fminf(L3[0], L3[1]);
    float L41 = fminf(L3[2], L3[3]);
    float M   = fminf(L40, L41);

    float M30 = fminf(L3[0], L3[2]);
    float M20 = fminf(fminf(L2[0], L2[2]), fminf(L2[4], L2[6]));
    float M10 = fminf(fminf(fminf(L1[0],  L1[2]),  fminf(L1[4],  L1[6])),
                      fminf(fminf(L1[8],  L1[10]), fminf(L1[12], L1[14])));
    float M00 = fminf(
        fminf(fminf(fminf(v[0],  v[2]),  fminf(v[4],  v[6])),
              fminf(fminf(v[8],  v[10]), fminf(v[12], v[14]))),
        fminf(fminf(fminf(v[16], v[18]), fminf(v[20], v[22])),
              fminf(fminf(v[24], v[26]), fminf(v[28], v[30]))));

    float s4 = (L40 > M) ? 1.0f : -1.0f;
    float s3 = (M30 > M) ? 1.0f : -1.0f;
    float s2 = (M20 > M) ? 1.0f : -1.0f;
    float s1 = (M10 > M) ? 1.0f : -1.0f;
    float s0 = (M00 > M) ? 1.0f : -1.0f;

    o[0] = s4;
    o[1] = s3;
    o[2] = s2;
    o[3] = s1;
    o[4] = s0;
    o[5] = -s0 * s4;
    o[6] = -s3 * s4;
    o[7] = -s2 * s3;
    o[8] = -s1 * s2;
    o[9] = -s0 * s1;
}

// process one 2-point (80B) group resident in shared at 'my'
__device__ __forceinline__ void process_pair(float4* my)
{
    float4 a = my[0], b = my[1], c = my[2], d = my[3], e = my[4];
    float x[20] = {a.x, a.y, a.z, a.w,  b.x, b.y, b.z, b.w,
                   c.x, c.y, c.z, c.w,  d.x, d.y, d.z, d.w,
                   e.x, e.y, e.z, e.w};
    float o[20];
    decide10(x,      o);
    decide10(x + 10, o + 10);
    my[0] = make_float4(o[0],  o[1],  o[2],  o[3]);
    my[1] = make_float4(o[4],  o[5],  o[6],  o[7]);
    my[2] = make_float4(o[8],  o[9],  o[10], o[11]);
    my[3] = make_float4(o[12], o[13], o[14], o[15]);
    my[4] = make_float4(o[16], o[17], o[18], o[19]);
}

__global__ __launch_bounds__(TPB)
void softdecision_kernel(const float* __restrict__ sig,
                         float* __restrict__ out,
                         int n_points)
{
    __shared__ float4 s[WARPS_PER_BLK][F4_PER_WARP];   // 40KB, reused in -> out

    const int lane = threadIdx.x & 31;
    const int wid  = threadIdx.x >> 5;
    const long long warp_pt0 = (long long)blockIdx.x * PTS_PER_BLK
                             + (long long)wid * PTS_PER_WARP;

    if (warp_pt0 + PTS_PER_WARP <= (long long)n_points) {
        // ---- fast path: whole 128-point tile in range ----
        const long long base4 = warp_pt0 * 10 / 4;     // float4 offset
        float4* sw = s[wid];

        // 10 back-to-back coalesced LDG.128 (MLP=10), then STS
        const float4* g = (const float4*)sig + base4;
        float4 r[10];
        #pragma unroll
        for (int i = 0; i < 10; i++) r[i] = __ldcs(g + lane + 32 * i);
        #pragma unroll
        for (int i = 0; i < 10; i++) sw[lane + 32 * i] = r[i];
        __syncwarp();

        // two 2-point groups per lane, both at the conflict-free 80B pattern
        process_pair(sw + lane * 5);          // points 2*lane, 2*lane+1
        process_pair(sw + 160 + lane * 5);    // points 64+2*lane, 65+2*lane
        __syncwarp();

        // 10 coalesced STG.128
        float4* go = (float4*)out + base4;
        #pragma unroll
        for (int i = 0; i < 10; i++) __stcs(go + lane + 32 * i, sw[lane + 32 * i]);
    } else {
        // ---- tail: per-point scalar path straight from/to global ----
        for (int q = 0; q < PPT; q++) {
            const long long p = warp_pt0 + (long long)lane * PPT + q;
            if (p < (long long)n_points) {
                float x[10], o[10];
                #pragma unroll
                for (int i = 0; i < 10; i++) x[i] = sig[p * 10 + i];
                decide10(x, o);
                #pragma unroll
                for (int i = 0; i < 10; i++) out[p * 10 + i] = o[i];
            }
        }
    }
}

extern "C" void kernel_launch(void* const* d_in, const int* in_sizes, int n_in,
                              void* d_out, int out_size)
{
    const float* signal = (const float*)d_in[0];
    // d_in[1] is the codebook; its structure is hardwired above.
    float* out = (float*)d_out;
    const int n_points = in_sizes[0] / 10;                              // 4,194,304
    const int n_blocks = (n_points + PTS_PER_BLK - 1) / PTS_PER_BLK;    // 4096
    softdecision_kernel<<<n_blocks, TPB>>>(signal, out, n_points);
}